// round 15
// baseline (speedup 1.0000x reference)
#include <cuda_runtime.h>
#include <cuda_fp16.h>

#define MDIM 1024
#define GR   32                 // rows per block = 32 warps x 1 row
#define TPB  1024

typedef unsigned int u32;
typedef unsigned short u16;

// row buffer (fp16 scalars): x[0,1024) | plus[1024,2048) | prod[2048,3072)
// 3072 halves = 6144 B per row, 32 rows = 196608 B.
#define ROW_BYTES  6144
#define BUF_BYTES  (32*ROW_BYTES)              // 196608
#define SIDX_OFF   (BUF_BYTES)                 // short4[M] remapped parents     8192
#define SWW_OFF    (SIDX_OFF + MDIM*8)         // u32[M] (w0,w1) packed half2    4096
#define SBH_OFF    (SWW_OFF  + MDIM*4)         // half[M] b'                     2048
#define WEPI_OFF   (SBH_OFF  + MDIM*2)         // float2[M] (wp',wq') permuted   8192
#define OFFS_OFF   (WEPI_OFF + MDIM*8)         // short[1026] level offsets      2056
#define SMEM_BYTES (OFFS_OFF + 2056)           // 221192 <= 232448 cap

__device__ __forceinline__ __half tanh_h(__half v) {
    u16 u = __half_as_ushort(v), r;
    asm("tanh.approx.f16 %0, %1;" : "=h"(r) : "h"(u));
    return __ushort_as_half(r);
}

// ---------------------------------------------------------------------------
// Fused kernel: 32 warps, ONE fp16 row per warp (8 warps/SMSP for maximum
// latency hiding — the binding resource per R5/R12/R14 evidence). Scalar
// half math; sigmoid = 0.5*tanh(z/2)+0.5 via tanh.approx.f16 with weights
// pre-halved at setup. Setup (exact DAG levels, counting sort, remap so
// stores are contiguous: enc(x,c)=c, enc(plus,s)=1024+pos, enc(prod,s)=
// 2048+pos in half units) is block-local as in prior rounds.
// ---------------------------------------------------------------------------
__global__ void __launch_bounds__(TPB, 1)
tree_kernel(const float* __restrict__ x,      const int* __restrict__ raw,
            const float* __restrict__ W_base, const float* __restrict__ b_base,
            const float* __restrict__ W_sig,  const float* __restrict__ b_sig,
            const float* __restrict__ w_plus, const float* __restrict__ b_plus,
            const float* __restrict__ w_prod, const float* __restrict__ b_prod,
            float* __restrict__ out, int nGroups)
{
    extern __shared__ char smraw[];
    short4*  sIdx = (short4*)(smraw + SIDX_OFF);
    u32*     sWw  = (u32*)   (smraw + SWW_OFF);
    __half*  sBh  = (__half*)(smraw + SBH_OFF);
    float2*  wepi = (float2*)(smraw + WEPI_OFF);
    short*   offs = (short*) (smraw + OFFS_OFF);

    // setup scratch overlaid on buffer region (released before staging rows)
    short4* sP   = (short4*)smraw;                       // [M] raw parents
    int*    lvl  = (int*)(smraw + 8192);
    int*    cnt  = (int*)(smraw + 12288);
    int*    cur  = (int*)(smraw + 16384);
    int*    posA = (int*)(smraw + 20480);

    int tid  = threadIdx.x;
    int lane = tid & 31;
    int wid  = tid >> 5;

    // ---- Phase 0: stage parents, zero counters ----------------------------
    for (int i = tid; i < MDIM; i += TPB) {
        short4 p;
        p.x = (short)raw[2*i];          p.y = (short)raw[2*i + 1];
        p.z = (short)raw[2*MDIM + 2*i]; p.w = (short)raw[2*MDIM + 2*i + 1];
        sP[i] = p;
        cnt[i] = 0;
    }
    __syncthreads();

    // ---- Phase 1: exact DAG levels, warp 0 over 32-step chunks ------------
    if (wid == 0) {
        for (int c = 0; c < MDIM/32; c++) {
            int idx  = c*32 + lane;
            int base = c*32;
            short4 p = sP[idx];
            int l = 0;
            int e0 = -1, e1 = -1, e2 = -1, e3 = -1;
            int q;
            q = p.x; if (q >= MDIM) { int pc = q & (MDIM-1); if (pc < base) l = max(l, lvl[pc]+1); else e0 = pc - base; }
            q = p.y; if (q >= MDIM) { int pc = q & (MDIM-1); if (pc < base) l = max(l, lvl[pc]+1); else e1 = pc - base; }
            q = p.z; if (q >= MDIM) { int pc = q & (MDIM-1); if (pc < base) l = max(l, lvl[pc]+1); else e2 = pc - base; }
            q = p.w; if (q >= MDIM) { int pc = q & (MDIM-1); if (pc < base) l = max(l, lvl[pc]+1); else e3 = pc - base; }
            for (;;) {
                int v0 = __shfl_sync(0xffffffffu, l, e0 < 0 ? 0 : e0);
                int v1 = __shfl_sync(0xffffffffu, l, e1 < 0 ? 0 : e1);
                int v2 = __shfl_sync(0xffffffffu, l, e2 < 0 ? 0 : e2);
                int v3 = __shfl_sync(0xffffffffu, l, e3 < 0 ? 0 : e3);
                int nl = l;
                if (e0 >= 0) nl = max(nl, v0 + 1);
                if (e1 >= 0) nl = max(nl, v1 + 1);
                if (e2 >= 0) nl = max(nl, v2 + 1);
                if (e3 >= 0) nl = max(nl, v3 + 1);
                unsigned ch = __ballot_sync(0xffffffffu, nl != l);
                l = nl;
                if (!ch) break;
            }
            lvl[idx] = l;
        }
    }
    __syncthreads();

    // ---- Phase 2: level histogram -----------------------------------------
    for (int i = tid; i < MDIM; i += TPB) atomicAdd(&cnt[lvl[i]], 1);
    __syncthreads();

    // ---- Phase 3: warp-0 scan -> level offsets ----------------------------
    if (wid == 0) {
        int carry = 0;
        for (int b = 0; b < MDIM; b += 32) {
            int v = cnt[b + lane];
            int s = v;
            #pragma unroll
            for (int o = 1; o < 32; o <<= 1) {
                int t = __shfl_up_sync(0xffffffffu, s, o);
                if (lane >= o) s += t;
            }
            int excl = carry + s - v;
            offs[b + lane] = (short)excl;
            cur[b + lane]  = excl;
            carry += __shfl_sync(0xffffffffu, s, 31);
        }
        if (lane == 0) { offs[MDIM] = MDIM; offs[MDIM+1] = MDIM; }
    }
    __syncthreads();

    // ---- Phase 4: schedule position of every step (block-local perm) ------
    for (int i = tid; i < MDIM; i += TPB) posA[i] = atomicAdd(&cur[lvl[i]], 1);
    __syncthreads();

    // ---- Phase 5: emit remapped packed schedule ---------------------------
    // enc in half units: x -> c ; plus(s) -> 1024+pos ; prod(s) -> 2048+pos
    for (int i = tid; i < MDIM; i += TPB) {
        short4 p = sP[i];
        int pos = posA[i];
        short4 v;
        int q;
        q = p.x; v.x = (short)(q < MDIM ? q : (q < 2*MDIM ? MDIM + posA[q - MDIM] : 2*MDIM + posA[q - 2*MDIM]));
        q = p.y; v.y = (short)(q < MDIM ? q : (q < 2*MDIM ? MDIM + posA[q - MDIM] : 2*MDIM + posA[q - 2*MDIM]));
        q = p.z; v.z = (short)(q < MDIM ? q : (q < 2*MDIM ? MDIM + posA[q - MDIM] : 2*MDIM + posA[q - 2*MDIM]));
        q = p.w; v.w = (short)(q < MDIM ? q : (q < 2*MDIM ? MDIM + posA[q - MDIM] : 2*MDIM + posA[q - 2*MDIM]));
        sIdx[pos] = v;
        __half2 ww = __floats2half2_rn(W_sig[2*i] * 0.5f, W_sig[2*i + 1] * 0.5f);
        sWw[pos] = *reinterpret_cast<u32*>(&ww);
        sBh[pos] = __float2half_rn(b_sig[i] * 0.5f);
        wepi[pos] = make_float2(w_plus[i], w_prod[i]);
    }
    __syncthreads();                     // last block-wide barrier

    // ---- Main: one warp per ROW, 32 warps, persistent over groups ---------
    __half* rb = (__half*)(smraw + wid * ROW_BYTES);
    float bias = b_base[0] + b_plus[0] + b_prod[0];
    const __half h05 = __float2half_rn(0.5f);

    for (int grp = blockIdx.x; grp < nGroups; grp += gridDim.x) {
        int row = grp * GR + wid;

        // stage x (fp32 coalesced float4 -> 4 halves), fold x.W_base in fp32
        const float4* xr  = (const float4*)(x + (size_t)row * MDIM);
        const float4* wb4 = (const float4*)W_base;
        float acc = 0.f;
        #pragma unroll
        for (int k = 0; k < 8; k++) {
            int p4 = lane + 32*k;               // float4 index 0..255
            float4 a  = xr[p4];
            float4 wv = wb4[p4];
            __half2 h01 = __floats2half2_rn(a.x, a.y);
            __half2 h23 = __floats2half2_rn(a.z, a.w);
            uint2 st;
            st.x = *reinterpret_cast<u32*>(&h01);
            st.y = *reinterpret_cast<u32*>(&h23);
            ((uint2*)rb)[p4] = st;
            acc = fmaf(a.x, wv.x, fmaf(a.y, wv.y, fmaf(a.z, wv.z, fmaf(a.w, wv.w, acc))));
        }
        __syncwarp();

        // level loop: scalar half math; contiguous STS.16 stores; next
        // level's schedule prefetched + unpacked before the syncwarp.
        int s0 = 0;
        int s1 = (int)offs[1];
        int ix, iy, iz, iw; __half w0, w1, bz;
        if (lane < s1) {
            short4 q = sIdx[lane];
            u32    ww = sWw[lane];
            __half2 w2 = *reinterpret_cast<__half2*>(&ww);
            ix = q.x; iy = q.y; iz = q.z; iw = q.w;
            w0 = __low2half(w2); w1 = __high2half(w2); bz = sBh[lane];
        }

        for (int L = 0; s0 < MDIM; L++) {
            int s2 = (int)offs[L + 2];
            int n = s1 - s0;
            if (lane < n) {                       // chunk 0 (prefetched)
                __half a0 = rb[ix], a1 = rb[iy];
                __half m0 = rb[iz], m1 = rb[iw];
                __half z  = __hfma(w0, a0, __hfma(w1, a1, bz));
                __half th = tanh_h(z);
                rb[2048 + s0 + lane] = __hmul(m0, m1);      // prod
                rb[1024 + s0 + lane] = __hfma(th, h05, h05);// plus
            }
            for (int cb = s0 + 32; cb < s1; cb += 32) {     // wide-level spill
                int sp = cb + lane;
                if (sp < s1) {
                    short4 q2 = sIdx[sp];
                    u32    ww2 = sWw[sp];
                    __half2 w22 = *reinterpret_cast<__half2*>(&ww2);
                    __half a0 = rb[q2.x], a1 = rb[q2.y];
                    __half m0 = rb[q2.z], m1 = rb[q2.w];
                    __half z  = __hfma(__low2half(w22), a0,
                                __hfma(__high2half(w22), a1, sBh[sp]));
                    __half th = tanh_h(z);
                    rb[2048 + sp] = __hmul(m0, m1);
                    rb[1024 + sp] = __hfma(th, h05, h05);
                }
            }
            {   // prefetch + unpack next level chunk 0 (pre-sync, off chain)
                int sp = s1 + lane;
                if (sp < s2) {
                    short4 q = sIdx[sp];
                    u32    ww = sWw[sp];
                    __half2 w2 = *reinterpret_cast<__half2*>(&ww);
                    ix = q.x; iy = q.y; iz = q.z; iw = q.w;
                    w0 = __low2half(w2); w1 = __high2half(w2); bz = sBh[sp];
                }
            }
            __syncwarp();
            s0 = s1; s1 = s2;
        }

        // epilogue: half2-vectorized dot over plus/prod regions.
        // lane handles value pairs (2m, 2m+1): wepi pairs load as float4.
        const __half2* pl2 = (const __half2*)(rb + 1024);
        const __half2* pr2 = (const __half2*)(rb + 2048);
        const float4*  we4 = (const float4*)wepi;
        for (int m = lane; m < 512; m += 32) {
            float2 pl = __half22float2(pl2[m]);
            float2 pr = __half22float2(pr2[m]);
            float4 we = we4[m];                  // (wp[2m],wq[2m],wp[2m+1],wq[2m+1])
            acc = fmaf(pl.x, we.x, fmaf(pr.x, we.y,
                  fmaf(pl.y, we.z, fmaf(pr.y, we.w, acc))));
        }
        #pragma unroll
        for (int o = 16; o; o >>= 1) acc += __shfl_xor_sync(0xffffffffu, acc, o);
        if (lane == 0) out[row] = acc + bias;
        __syncwarp();
    }
}

// ---------------------------------------------------------------------------
extern "C" void kernel_launch(void* const* d_in, const int* in_sizes, int n_in,
                              void* d_out, int out_size) {
    const float* x  = (const float*)d_in[0];
    const int*   ri = (const int*)  d_in[1];
    const float* Wb = (const float*)d_in[2];
    const float* bb = (const float*)d_in[3];
    const float* Ws = (const float*)d_in[4];
    const float* bs = (const float*)d_in[5];
    const float* wp = (const float*)d_in[6];
    const float* bp = (const float*)d_in[7];
    const float* wq = (const float*)d_in[8];
    const float* bq = (const float*)d_in[9];
    float* out = (float*)d_out;

    int B = in_sizes[0] / MDIM;          // 8192
    int nGroups = B / GR;                // 256

    static int sm_count = 0;
    if (sm_count == 0) {
        int dev = 0;
        cudaGetDevice(&dev);
        cudaDeviceGetAttribute(&sm_count, cudaDevAttrMultiProcessorCount, dev);
        if (sm_count <= 0) sm_count = 148;
        cudaFuncSetAttribute(tree_kernel,
                             cudaFuncAttributeMaxDynamicSharedMemorySize, SMEM_BYTES);
    }
    int grid = nGroups < sm_count ? nGroups : sm_count;

    tree_kernel<<<grid, TPB, SMEM_BYTES>>>(x, ri, Wb, bb, Ws, bs, wp, bp, wq, bq,
                                           out, nGroups);
}

// round 16
// speedup vs baseline: 1.2557x; 1.2557x over previous
#include <cuda_runtime.h>
#include <cuda_fp16.h>

#define MDIM 1024
#define GR   32                 // rows per block = 16 warps x 2 rows (half2-packed)
#define TPB  512
#define PAIRSTRIDE (3*MDIM)     // half2 units per pair buffer: [x | plus | prod]

typedef unsigned int u32;

// persistent shared layout (pair buffers are half2: 12KB per pair, 16 pairs)
#define BUF_BYTES  (16*PAIRSTRIDE*4)           // 196608
#define SREC_OFF   (BUF_BYTES)                 // uint4[M] fused records        16384
#define WEPI_OFF   (SREC_OFF + MDIM*16)        // float2[M] (wp',wq') permuted   8192
#define OFFS_OFF   (WEPI_OFF + MDIM*8)         // short[1026] level offsets      2056
#define SMEM_BYTES (OFFS_OFF + 2056)           // 223240 <= 232448 cap

__device__ __forceinline__ __half2 tanh2_approx(__half2 v) {
    u32 u = *reinterpret_cast<u32*>(&v);
    u32 r;
    asm("tanh.approx.f16x2 %0, %1;" : "=r"(r) : "r"(u));
    return *reinterpret_cast<__half2*>(&r);
}

// ---------------------------------------------------------------------------
// R12 structure (16 warps x 2 rows/warp in half2 — the measured optimum) with
// the per-step schedule fused into ONE 16-byte record:
//   rec.x = (idx0 | idx1<<16)   rec.y = (idx2 | idx3<<16)
//   rec.z = w0,w1 as half2 (pre-halved for the tanh identity)
//   rec.w = b broadcast half2 (pre-halved)
// One LDS.128 prefetch per level replaces 3 separate LDS ops. Sigmoid via
// tanh.approx.f16x2 (sigma(z)=0.5*tanh(z/2)+0.5); prod via HMUL2. Setup
// (exact DAG levels, counting sort, remap: enc(x,c)=c, enc(plus,s)=1024+pos,
// enc(prod,s)=2048+pos in half2 words) block-local as before.
// ---------------------------------------------------------------------------
__global__ void __launch_bounds__(TPB, 1)
tree_kernel(const float* __restrict__ x,      const int* __restrict__ raw,
            const float* __restrict__ W_base, const float* __restrict__ b_base,
            const float* __restrict__ W_sig,  const float* __restrict__ b_sig,
            const float* __restrict__ w_plus, const float* __restrict__ b_plus,
            const float* __restrict__ w_prod, const float* __restrict__ b_prod,
            float* __restrict__ out, int nGroups)
{
    extern __shared__ char smraw[];
    __half2* buf  = (__half2*)smraw;                     // [16][PAIRSTRIDE]
    uint4*   sRec = (uint4*) (smraw + SREC_OFF);
    float2*  wepi = (float2*)(smraw + WEPI_OFF);
    short*   offs = (short*) (smraw + OFFS_OFF);

    // setup scratch overlaid on buf (released before staging rows)
    short4* sP   = (short4*)smraw;                       // [M] raw parents
    int*    lvl  = (int*)(smraw + 8192);
    int*    cnt  = (int*)(smraw + 12288);
    int*    cur  = (int*)(smraw + 16384);
    int*    posA = (int*)(smraw + 20480);

    int tid  = threadIdx.x;
    int lane = tid & 31;
    int wid  = tid >> 5;

    // ---- Phase 0: stage parents, zero counters ----------------------------
    for (int i = tid; i < MDIM; i += TPB) {
        short4 p;
        p.x = (short)raw[2*i];          p.y = (short)raw[2*i + 1];
        p.z = (short)raw[2*MDIM + 2*i]; p.w = (short)raw[2*MDIM + 2*i + 1];
        sP[i] = p;
        cnt[i] = 0;
    }
    __syncthreads();

    // ---- Phase 1: exact DAG levels, warp 0 over 32-step chunks ------------
    if (wid == 0) {
        for (int c = 0; c < MDIM/32; c++) {
            int idx  = c*32 + lane;
            int base = c*32;
            short4 p = sP[idx];
            int l = 0;
            int e0 = -1, e1 = -1, e2 = -1, e3 = -1;
            int q;
            q = p.x; if (q >= MDIM) { int pc = q & (MDIM-1); if (pc < base) l = max(l, lvl[pc]+1); else e0 = pc - base; }
            q = p.y; if (q >= MDIM) { int pc = q & (MDIM-1); if (pc < base) l = max(l, lvl[pc]+1); else e1 = pc - base; }
            q = p.z; if (q >= MDIM) { int pc = q & (MDIM-1); if (pc < base) l = max(l, lvl[pc]+1); else e2 = pc - base; }
            q = p.w; if (q >= MDIM) { int pc = q & (MDIM-1); if (pc < base) l = max(l, lvl[pc]+1); else e3 = pc - base; }
            for (;;) {
                int v0 = __shfl_sync(0xffffffffu, l, e0 < 0 ? 0 : e0);
                int v1 = __shfl_sync(0xffffffffu, l, e1 < 0 ? 0 : e1);
                int v2 = __shfl_sync(0xffffffffu, l, e2 < 0 ? 0 : e2);
                int v3 = __shfl_sync(0xffffffffu, l, e3 < 0 ? 0 : e3);
                int nl = l;
                if (e0 >= 0) nl = max(nl, v0 + 1);
                if (e1 >= 0) nl = max(nl, v1 + 1);
                if (e2 >= 0) nl = max(nl, v2 + 1);
                if (e3 >= 0) nl = max(nl, v3 + 1);
                unsigned ch = __ballot_sync(0xffffffffu, nl != l);
                l = nl;
                if (!ch) break;
            }
            lvl[idx] = l;
        }
    }
    __syncthreads();

    // ---- Phase 2: level histogram -----------------------------------------
    for (int i = tid; i < MDIM; i += TPB) atomicAdd(&cnt[lvl[i]], 1);
    __syncthreads();

    // ---- Phase 3: warp-0 scan -> level offsets ----------------------------
    if (wid == 0) {
        int carry = 0;
        for (int b = 0; b < MDIM; b += 32) {
            int v = cnt[b + lane];
            int s = v;
            #pragma unroll
            for (int o = 1; o < 32; o <<= 1) {
                int t = __shfl_up_sync(0xffffffffu, s, o);
                if (lane >= o) s += t;
            }
            int excl = carry + s - v;
            offs[b + lane] = (short)excl;
            cur[b + lane]  = excl;
            carry += __shfl_sync(0xffffffffu, s, 31);
        }
        if (lane == 0) { offs[MDIM] = MDIM; offs[MDIM+1] = MDIM; }
    }
    __syncthreads();

    // ---- Phase 4: schedule position of every step (block-local perm) ------
    for (int i = tid; i < MDIM; i += TPB) posA[i] = atomicAdd(&cur[lvl[i]], 1);
    __syncthreads();

    // ---- Phase 5: emit fused 16-byte schedule records ---------------------
    // enc in half2 words: x -> c ; plus(s) -> 1024+pos ; prod(s) -> 2048+pos
    for (int i = tid; i < MDIM; i += TPB) {
        short4 p = sP[i];
        int pos = posA[i];
        int q, i0, i1, i2, i3;
        q = p.x; i0 = (q < MDIM) ? q : (q < 2*MDIM ? MDIM + posA[q - MDIM] : 2*MDIM + posA[q - 2*MDIM]);
        q = p.y; i1 = (q < MDIM) ? q : (q < 2*MDIM ? MDIM + posA[q - MDIM] : 2*MDIM + posA[q - 2*MDIM]);
        q = p.z; i2 = (q < MDIM) ? q : (q < 2*MDIM ? MDIM + posA[q - MDIM] : 2*MDIM + posA[q - 2*MDIM]);
        q = p.w; i3 = (q < MDIM) ? q : (q < 2*MDIM ? MDIM + posA[q - MDIM] : 2*MDIM + posA[q - 2*MDIM]);
        __half2 hw = __floats2half2_rn(W_sig[2*i] * 0.5f, W_sig[2*i + 1] * 0.5f);
        __half2 hb = __float2half2_rn(b_sig[i] * 0.5f);
        uint4 rec;
        rec.x = (u32)i0 | ((u32)i1 << 16);
        rec.y = (u32)i2 | ((u32)i3 << 16);
        rec.z = *reinterpret_cast<u32*>(&hw);
        rec.w = *reinterpret_cast<u32*>(&hb);
        sRec[pos] = rec;
        wepi[pos] = make_float2(w_plus[i], w_prod[i]);   // block-consistent
    }
    __syncthreads();                     // last block-wide barrier

    // ---- Main: one warp per ROW-PAIR, persistent over groups --------------
    __half2* pb = buf + wid * PAIRSTRIDE;    // x[0,M) plus[M,2M) prod[2M,3M)
    float bias = b_base[0] + b_plus[0] + b_prod[0];
    const __half2 H05 = __floats2half2_rn(0.5f, 0.5f);

    for (int grp = blockIdx.x; grp < nGroups; grp += gridDim.x) {
        int rowA = grp * GR + 2*wid;

        // stage both rows (fp32 coalesced), pack half2, fold x.W_base in fp32
        const float4* xrA = (const float4*)(x + (size_t)rowA * MDIM);
        const float4* xrB = (const float4*)(x + (size_t)(rowA + 1) * MDIM);
        const float4* wb4 = (const float4*)W_base;
        float accA = 0.f, accB = 0.f;
        #pragma unroll
        for (int k = 0; k < MDIM/128; k++) {
            float4 a  = xrA[lane + 32*k];
            float4 b  = xrB[lane + 32*k];
            float4 wv = wb4[lane + 32*k];
            __half2 h[4];
            h[0] = __floats2half2_rn(a.x, b.x);
            h[1] = __floats2half2_rn(a.y, b.y);
            h[2] = __floats2half2_rn(a.z, b.z);
            h[3] = __floats2half2_rn(a.w, b.w);
            ((uint4*)pb)[lane + 32*k] = *(const uint4*)h;
            accA = fmaf(a.x, wv.x, fmaf(a.y, wv.y, fmaf(a.z, wv.z, fmaf(a.w, wv.w, accA))));
            accB = fmaf(b.x, wv.x, fmaf(b.y, wv.y, fmaf(b.z, wv.z, fmaf(b.w, wv.w, accB))));
        }
        __syncwarp();

        // level loop: single LDS.128 record prefetch per level, unpacked to
        // registers pre-sync (off the dependent chain); f16x2 math serves
        // both rows per instruction; contiguous STS.32 stores.
        int s0 = 0;
        int s1 = (int)offs[1];
        int ix, iy, iz, iw; __half2 w0x2, bx2;
        if (lane < s1) {
            uint4 r = sRec[lane];
            ix = (int)(r.x & 0xFFFFu); iy = (int)(r.x >> 16);
            iz = (int)(r.y & 0xFFFFu); iw = (int)(r.y >> 16);
            w0x2 = *reinterpret_cast<__half2*>(&r.z);
            bx2  = *reinterpret_cast<__half2*>(&r.w);
        }

        for (int L = 0; s0 < MDIM; L++) {
            int s2 = (int)offs[L + 2];
            int n = s1 - s0;
            if (lane < n) {                       // chunk 0 (prefetched)
                __half2 a0 = pb[ix], a1 = pb[iy];
                __half2 m0 = pb[iz], m1 = pb[iw];
                // z = w0*a0 + w1*a1 + b  with w0=lo(w0x2) bcast, w1=hi(w0x2) bcast
                __half2 wlo = __low2half2(w0x2);
                __half2 whi = __high2half2(w0x2);
                __half2 z  = __hfma2(wlo, a0, __hfma2(whi, a1, bx2));
                __half2 th = tanh2_approx(z);
                pb[2048 + s0 + lane] = __hmul2(m0, m1);        // prod
                pb[1024 + s0 + lane] = __hfma2(th, H05, H05);  // plus
            }
            for (int cb = s0 + 32; cb < s1; cb += 32) {    // rare wide levels
                int sp = cb + lane;
                if (sp < s1) {
                    uint4 r2 = sRec[sp];
                    int jx = (int)(r2.x & 0xFFFFu), jy = (int)(r2.x >> 16);
                    int jz = (int)(r2.y & 0xFFFFu), jw = (int)(r2.y >> 16);
                    __half2 wv = *reinterpret_cast<__half2*>(&r2.z);
                    __half2 bv = *reinterpret_cast<__half2*>(&r2.w);
                    __half2 a0 = pb[jx], a1 = pb[jy];
                    __half2 m0 = pb[jz], m1 = pb[jw];
                    __half2 z  = __hfma2(__low2half2(wv), a0,
                                 __hfma2(__high2half2(wv), a1, bv));
                    __half2 th = tanh2_approx(z);
                    pb[2048 + sp] = __hmul2(m0, m1);
                    pb[1024 + sp] = __hfma2(th, H05, H05);
                }
            }
            {   // prefetch + unpack next level chunk 0 (pre-sync, off chain)
                int sp = s1 + lane;
                if (sp < s2) {
                    uint4 r = sRec[sp];
                    ix = (int)(r.x & 0xFFFFu); iy = (int)(r.x >> 16);
                    iz = (int)(r.y & 0xFFFFu); iw = (int)(r.y >> 16);
                    w0x2 = *reinterpret_cast<__half2*>(&r.z);
                    bx2  = *reinterpret_cast<__half2*>(&r.w);
                }
            }
            __syncwarp();
            s0 = s1; s1 = s2;
        }

        // epilogue: both rows' plus/prod dots (stride-32, conflict-free)
        for (int m = lane; m < MDIM; m += 32) {
            float2 pl = __half22float2(pb[1024 + m]);
            float2 pr = __half22float2(pb[2048 + m]);
            float2 we = wepi[m];
            accA = fmaf(pl.x, we.x, fmaf(pr.x, we.y, accA));
            accB = fmaf(pl.y, we.x, fmaf(pr.y, we.y, accB));
        }
        #pragma unroll
        for (int o = 16; o; o >>= 1) {
            accA += __shfl_xor_sync(0xffffffffu, accA, o);
            accB += __shfl_xor_sync(0xffffffffu, accB, o);
        }
        if (lane == 0) {
            out[rowA]     = accA + bias;
            out[rowA + 1] = accB + bias;
        }
        __syncwarp();
    }
}

// ---------------------------------------------------------------------------
extern "C" void kernel_launch(void* const* d_in, const int* in_sizes, int n_in,
                              void* d_out, int out_size) {
    const float* x  = (const float*)d_in[0];
    const int*   ri = (const int*)  d_in[1];
    const float* Wb = (const float*)d_in[2];
    const float* bb = (const float*)d_in[3];
    const float* Ws = (const float*)d_in[4];
    const float* bs = (const float*)d_in[5];
    const float* wp = (const float*)d_in[6];
    const float* bp = (const float*)d_in[7];
    const float* wq = (const float*)d_in[8];
    const float* bq = (const float*)d_in[9];
    float* out = (float*)d_out;

    int B = in_sizes[0] / MDIM;          // 8192
    int nGroups = B / GR;                // 256

    static int sm_count = 0;
    if (sm_count == 0) {
        int dev = 0;
        cudaGetDevice(&dev);
        cudaDeviceGetAttribute(&sm_count, cudaDevAttrMultiProcessorCount, dev);
        if (sm_count <= 0) sm_count = 148;
        cudaFuncSetAttribute(tree_kernel,
                             cudaFuncAttributeMaxDynamicSharedMemorySize, SMEM_BYTES);
    }
    int grid = nGroups < sm_count ? nGroups : sm_count;

    tree_kernel<<<grid, TPB, SMEM_BYTES>>>(x, ri, Wb, bb, Ws, bs, wp, bp, wq, bq,
                                           out, nGroups);
}